// round 7
// baseline (speedup 1.0000x reference)
#include <cuda_runtime.h>
#include <cuda_fp16.h>

// Problem constants
#define NB   32      // batch
#define NIN  2048    // input capsules
#define ROW  1024    // NOUT*DD floats per (b,i) row
#define SLICES 8     // blocks per batch item (grid 256 = one wave @ 2 blocks/SM)
#define WPBLK  8     // warps per block
#define IPW  32      // input rows per warp (NIN / (SLICES*WPBLK))

// Scratch (static device memory; no runtime allocation)
__device__ float  g_partials[NB * SLICES * ROW];      // 1 MB, L2-resident
__device__ float  g_ow[NB * ROW];                     // out0 / out0+out1
__device__ float4 g_xh[(size_t)NB * NIN * 128];       // fp16 shadow of x, 128 MB (16B-aligned)
__device__ int    g_cnt[NB];                          // zero-init; self-resetting

// ---------------------------------------------------------------------------
// Common tail: caller has filled sbuf[wloc*256 + t'] with its accumulators.
// In-block reduce -> per-block partial; last block per batch reduces SLICES
// partials in fixed order, adds bias, squashes, updates g_ow / output.
// ---------------------------------------------------------------------------
template<int OW_MODE, int FINAL_OUT>
__device__ __forceinline__ void tail_common(
    int b, int slice, float4* sbuf,
    const float* __restrict__ bias, float* __restrict__ dout)
{
    __syncthreads();

    const int t = threadIdx.x;
    float4 s = make_float4(0.f, 0.f, 0.f, 0.f);
#pragma unroll
    for (int w2 = 0; w2 < WPBLK; w2++) {
        float4 v = sbuf[w2 * 256 + t];
        s.x += v.x; s.y += v.y; s.z += v.z; s.w += v.w;
    }
    reinterpret_cast<float4*>(g_partials)[((size_t)b * SLICES + slice) * 256 + t] = s;
    __threadfence();

    __shared__ int isLast;
    if (t == 0) {
        int old = atomicAdd(&g_cnt[b], 1);
        isLast = (old == SLICES - 1);
    }
    __syncthreads();
    if (!isLast) return;

    const float4* pp = reinterpret_cast<const float4*>(g_partials) + (size_t)b * SLICES * 256;
    float4 r = make_float4(0.f, 0.f, 0.f, 0.f);
#pragma unroll
    for (int s2 = 0; s2 < SLICES; s2++) {
        float4 v = __ldcg(pp + s2 * 256 + t);
        r.x += v.x; r.y += v.y; r.z += v.z; r.w += v.w;
    }
    float4 bb = reinterpret_cast<const float4*>(bias)[t];
    r.x += bb.x; r.y += bb.y; r.z += bb.z; r.w += bb.w;

    // squash over d=16 (4 threads per capsule j)
    float n2 = r.x * r.x + r.y * r.y + r.z * r.z + r.w * r.w;
    n2 += __shfl_xor_sync(0xffffffffu, n2, 1);
    n2 += __shfl_xor_sync(0xffffffffu, n2, 2);
    float scale = n2 / ((1.0f + n2) * sqrtf(n2 + 1e-7f));
    float4 o = make_float4(r.x * scale, r.y * scale, r.z * scale, r.w * scale);

    if (FINAL_OUT)
        reinterpret_cast<float4*>(dout)[b * 256 + t] = o;
    if (OW_MODE == 1) {
        reinterpret_cast<float4*>(g_ow)[b * 256 + t] = o;
    } else if (OW_MODE == 2) {
        float4 c = reinterpret_cast<const float4*>(g_ow)[b * 256 + t];
        c.x += o.x; c.y += o.y; c.z += o.z; c.w += o.w;
        reinterpret_cast<float4*>(g_ow)[b * 256 + t] = c;
    }

    if (t == 0) g_cnt[b] = 0;   // replay-safe reset
}

// ---------------------------------------------------------------------------
// Pass 0: uniform weights (softmax of zero priors = 1/64). Reads fp32 with
// __ldcs (evict-first: keep L2 free for the shadow), writes fp16 shadow with
// plain stores (evict-normal: retained in L2 for pass 1).
// fp32 mapping: float4 f = lane + 32k -> elements [4f, 4f+4).
// ---------------------------------------------------------------------------
__global__ void __launch_bounds__(256, 2)
pass0(const float* __restrict__ x, const float* __restrict__ bias,
      float* __restrict__ dout)
{
    const int b     = blockIdx.x >> 3;
    const int slice = blockIdx.x & 7;
    const int wloc  = threadIdx.x >> 5;
    const int wb    = (slice << 3) | wloc;
    const int lane  = threadIdx.x & 31;

    float4 acc[8];
#pragma unroll
    for (int k = 0; k < 8; k++) acc[k] = make_float4(0.f, 0.f, 0.f, 0.f);

    const float4* base = reinterpret_cast<const float4*>(x)
        + ((size_t)b * NIN + (size_t)wb * IPW) * 256;
    float2* hbase = reinterpret_cast<float2*>(g_xh)
        + ((size_t)b * NIN + (size_t)wb * IPW) * 256;   // 256 float2 (=4 halves) per row

    for (int ii = 0; ii < IPW; ii++) {
        const float4* rowp = base + (size_t)ii * 256;
        float2* hrow = hbase + (size_t)ii * 256;
#pragma unroll
        for (int k = 0; k < 8; k++) {
            float4 v = __ldcs(rowp + lane + 32 * k);
            // fp16 shadow (plain store -> evict-normal, stays in L2)
            __half2 h0 = __floats2half2_rn(v.x, v.y);
            __half2 h1 = __floats2half2_rn(v.z, v.w);
            float2 st;
            st.x = __uint_as_float(*reinterpret_cast<unsigned*>(&h0));
            st.y = __uint_as_float(*reinterpret_cast<unsigned*>(&h1));
            hrow[lane + 32 * k] = st;
            acc[k].x += v.x; acc[k].y += v.y; acc[k].z += v.z; acc[k].w += v.w;
        }
    }
#pragma unroll
    for (int k = 0; k < 8; k++) {
        acc[k].x *= 0.015625f; acc[k].y *= 0.015625f;   // 1/64 exact
        acc[k].z *= 0.015625f; acc[k].w *= 0.015625f;
    }

    __shared__ float4 sbuf[WPBLK * 256];
#pragma unroll
    for (int k = 0; k < 8; k++) sbuf[wloc * 256 + lane + 32 * k] = acc[k];

    tail_common<1, 0>(b, slice, sbuf, bias, dout);
}

// ---------------------------------------------------------------------------
// Passes 1 & 2: read fp16 shadow with LDG.128 (float4 = 8 halves).
// Mapping: float4 g = lane + 32k' (k'=0..3) -> halves [8g, 8g+8)
//   -> capsule j = (lane>>1) + 16k', d = (lane&1)*8 .. +8.
// Dot over d=16: reduce across lane pair (xor 1). Softmax over 64 j:
// max/sum over k' then xor 2,4,8,16.
// REVERSE: back-to-front traversal (zigzag L2 reuse across passes).
// ---------------------------------------------------------------------------
template<int OW_MODE, int FINAL_OUT, int REVERSE>
__global__ void __launch_bounds__(256, 2)
passH(const float* __restrict__ bias, float* __restrict__ dout)
{
    const int b     = blockIdx.x >> 3;
    const int slice = blockIdx.x & 7;
    const int wloc  = threadIdx.x >> 5;
    const int wb    = (slice << 3) | wloc;
    const int lane  = threadIdx.x & 31;

    // fp32 weights for this thread's elements: float4 pairs at f = 2g, 2g+1
    const float4* owp = reinterpret_cast<const float4*>(g_ow) + (size_t)b * 256;
    float4 w[8];
#pragma unroll
    for (int k = 0; k < 4; k++) {
        int g = lane + 32 * k;
        w[2 * k]     = owp[2 * g];
        w[2 * k + 1] = owp[2 * g + 1];
    }

    float4 acc[8];
#pragma unroll
    for (int k = 0; k < 8; k++) acc[k] = make_float4(0.f, 0.f, 0.f, 0.f);

    const float4* hbase = g_xh + ((size_t)b * NIN + (size_t)wb * IPW) * 128;  // 128 float4/row

    for (int it = 0; it < IPW; it++) {
        const int ii = REVERSE ? (IPW - 1 - it) : it;
        const float4* hrow = hbase + (size_t)ii * 128;

        float4 xv[8];
#pragma unroll
        for (int k = 0; k < 4; k++) {
            float4 hv = hrow[lane + 32 * k];            // 8 halves, plain load (L2 retain)
            const __half2* hh = reinterpret_cast<const __half2*>(&hv);
            float2 a0 = __half22float2(hh[0]);
            float2 a1 = __half22float2(hh[1]);
            float2 a2 = __half22float2(hh[2]);
            float2 a3 = __half22float2(hh[3]);
            xv[2 * k]     = make_float4(a0.x, a0.y, a1.x, a1.y);
            xv[2 * k + 1] = make_float4(a2.x, a2.y, a3.x, a3.y);
        }

        float p[4];
#pragma unroll
        for (int k = 0; k < 4; k++) {
            float t = xv[2 * k].x * w[2 * k].x + xv[2 * k].y * w[2 * k].y
                    + xv[2 * k].z * w[2 * k].z + xv[2 * k].w * w[2 * k].w
                    + xv[2 * k + 1].x * w[2 * k + 1].x + xv[2 * k + 1].y * w[2 * k + 1].y
                    + xv[2 * k + 1].z * w[2 * k + 1].z + xv[2 * k + 1].w * w[2 * k + 1].w;
            t += __shfl_xor_sync(0xffffffffu, t, 1);    // full dot over d=16 (lane pair)
            p[k] = t;
        }
        // softmax over all 64 j
        float m = fmaxf(fmaxf(p[0], p[1]), fmaxf(p[2], p[3]));
        m = fmaxf(m, __shfl_xor_sync(0xffffffffu, m, 2));
        m = fmaxf(m, __shfl_xor_sync(0xffffffffu, m, 4));
        m = fmaxf(m, __shfl_xor_sync(0xffffffffu, m, 8));
        m = fmaxf(m, __shfl_xor_sync(0xffffffffu, m, 16));
        float a[4], s = 0.f;
#pragma unroll
        for (int k = 0; k < 4; k++) { a[k] = __expf(p[k] - m); s += a[k]; }
        s += __shfl_xor_sync(0xffffffffu, s, 2);
        s += __shfl_xor_sync(0xffffffffu, s, 4);
        s += __shfl_xor_sync(0xffffffffu, s, 8);
        s += __shfl_xor_sync(0xffffffffu, s, 16);
        float inv = 1.0f / s;
#pragma unroll
        for (int k = 0; k < 4; k++) {
            float ak = a[k] * inv;
            acc[2 * k].x     = fmaf(ak, xv[2 * k].x,     acc[2 * k].x);
            acc[2 * k].y     = fmaf(ak, xv[2 * k].y,     acc[2 * k].y);
            acc[2 * k].z     = fmaf(ak, xv[2 * k].z,     acc[2 * k].z);
            acc[2 * k].w     = fmaf(ak, xv[2 * k].w,     acc[2 * k].w);
            acc[2 * k + 1].x = fmaf(ak, xv[2 * k + 1].x, acc[2 * k + 1].x);
            acc[2 * k + 1].y = fmaf(ak, xv[2 * k + 1].y, acc[2 * k + 1].y);
            acc[2 * k + 1].z = fmaf(ak, xv[2 * k + 1].z, acc[2 * k + 1].z);
            acc[2 * k + 1].w = fmaf(ak, xv[2 * k + 1].w, acc[2 * k + 1].w);
        }
    }

    // write accumulators to sbuf in canonical float4-position order
    __shared__ float4 sbuf[WPBLK * 256];
#pragma unroll
    for (int k = 0; k < 4; k++) {
        int g = lane + 32 * k;
        sbuf[wloc * 256 + 2 * g]     = acc[2 * k];
        sbuf[wloc * 256 + 2 * g + 1] = acc[2 * k + 1];
    }

    tail_common<OW_MODE, FINAL_OUT>(b, slice, sbuf, bias, dout);
}

extern "C" void kernel_launch(void* const* d_in, const int* in_sizes, int n_in,
                              void* d_out, int out_size)
{
    const float* x    = (const float*)d_in[0];   // [32, 2048, 64, 16]
    const float* bias = (const float*)d_in[1];   // [64, 16]
    float* out = (float*)d_out;                  // [32, 64, 16]

    (void)in_sizes; (void)n_in; (void)out_size;

    dim3 g(NB * SLICES), blk(256);

    // Round 0 (forward, fp32): uniform weights; also emit fp16 shadow; g_ow = out0
    pass0<<<g, blk>>>(x, bias, out);
    // Round 1 (REVERSE, fp16): softmax(dot(x, out0)); g_ow = out0 + out1
    passH<2, 0, 1><<<g, blk>>>(bias, out);
    // Round 2 (forward, fp16): softmax(dot(x, out0+out1)); write output
    passH<0, 1, 0><<<g, blk>>>(bias, out);
}

// round 8
// speedup vs baseline: 1.5171x; 1.5171x over previous
#include <cuda_runtime.h>

// Problem constants
#define NB   32      // batch
#define NIN  2048    // input capsules
#define ROW  1024    // NOUT*DD floats per (b,i) row
#define SLICES 8     // blocks per batch item
#define WPBLK  8     // warps per block
#define IPW  32      // input rows per warp (NIN / (SLICES*WPBLK))
#define GRID (NB * SLICES)   // 256 blocks = single resident wave @ 2 blocks/SM

// Scratch (static device memory; no runtime allocation)
__device__ float g_partials[NB * SLICES * ROW];  // 1 MB, L2-resident
__device__ float g_ow[NB * ROW];                 // out0 (phase1) / out0+out1 (phase2)
__device__ int   g_cnt[NB];                      // zero-init; self-resetting
__device__ volatile unsigned g_epoch;            // monotonic barrier epoch (replay-safe)
__device__ unsigned g_arrive;                    // arrive counter; reset by last arriver

// ---------------------------------------------------------------------------
// Grid-wide barrier (sense-reversal via monotonic epoch). All 256 blocks are
// resident (2/SM * 148 SMs = 296 slots), so spinning is deadlock-free.
// Every thread fences before arrival so all phase writes are device-visible.
// ---------------------------------------------------------------------------
__device__ __forceinline__ void grid_barrier()
{
    __threadfence();          // publish this thread's phase writes
    __syncthreads();
    if (threadIdx.x == 0) {
        unsigned e = g_epoch;
        unsigned old = atomicAdd(&g_arrive, 1u);
        if (old == GRID - 1) {
            g_arrive = 0;     // reset BEFORE epoch bump
            __threadfence();
            atomicAdd((unsigned*)&g_epoch, 1u);
        } else {
            while (g_epoch == e) __nanosleep(64);
        }
    }
    __syncthreads();
    __threadfence();          // acquire: order subsequent reads after the spin
}

// ---------------------------------------------------------------------------
// Fused tail: in-block reduce (8 warps -> 1 partial per block), then the LAST
// block of each batch reduces the SLICES partials in fixed order, adds bias,
// squashes, updates g_ow / writes output, resets the counter (replay-safe).
// ---------------------------------------------------------------------------
template<int OW_MODE, int FINAL_OUT>
__device__ __forceinline__ void finish_tail(
    int b, int slice, float4 acc[8], int wloc, int lane,
    const float* __restrict__ bias, float* __restrict__ dout, float4* sbuf)
{
    __syncthreads();   // sbuf may still be read by the previous phase's tail
#pragma unroll
    for (int k = 0; k < 8; k++) sbuf[wloc * 256 + lane + 32 * k] = acc[k];
    __syncthreads();

    const int t = threadIdx.x;
    float4 s = make_float4(0.f, 0.f, 0.f, 0.f);
#pragma unroll
    for (int w2 = 0; w2 < WPBLK; w2++) {
        float4 v = sbuf[w2 * 256 + t];
        s.x += v.x; s.y += v.y; s.z += v.z; s.w += v.w;
    }
    reinterpret_cast<float4*>(g_partials)[((size_t)b * SLICES + slice) * 256 + t] = s;
    __threadfence();

    __shared__ int isLast;
    if (t == 0) {
        int old = atomicAdd(&g_cnt[b], 1);
        isLast = (old == SLICES - 1);
    }
    __syncthreads();
    if (!isLast) return;

    // Last block for this batch: all partials visible (fence + atomic order).
    const float4* pp = reinterpret_cast<const float4*>(g_partials) + (size_t)b * SLICES * 256;
    float4 r = make_float4(0.f, 0.f, 0.f, 0.f);
#pragma unroll
    for (int s2 = 0; s2 < SLICES; s2++) {
        float4 v = __ldcg(pp + s2 * 256 + t);
        r.x += v.x; r.y += v.y; r.z += v.z; r.w += v.w;
    }
    float4 bb = reinterpret_cast<const float4*>(bias)[t];
    r.x += bb.x; r.y += bb.y; r.z += bb.z; r.w += bb.w;

    // squash over d=16 (4 threads per capsule j)
    float n2 = r.x * r.x + r.y * r.y + r.z * r.z + r.w * r.w;
    n2 += __shfl_xor_sync(0xffffffffu, n2, 1);
    n2 += __shfl_xor_sync(0xffffffffu, n2, 2);
    float scale = n2 / ((1.0f + n2) * sqrtf(n2 + 1e-7f));
    float4 o = make_float4(r.x * scale, r.y * scale, r.z * scale, r.w * scale);

    if (FINAL_OUT)
        reinterpret_cast<float4*>(dout)[b * 256 + t] = o;
    if (OW_MODE == 1) {
        reinterpret_cast<float4*>(g_ow)[b * 256 + t] = o;
    } else if (OW_MODE == 2) {
        float4 c = reinterpret_cast<const float4*>(g_ow)[b * 256 + t];
        c.x += o.x; c.y += o.y; c.z += o.z; c.w += o.w;
        reinterpret_cast<float4*>(g_ow)[b * 256 + t] = c;
    }

    if (t == 0) g_cnt[b] = 0;   // reset for next phase / next graph replay
}

// ---------------------------------------------------------------------------
// Phase 0: uniform weights (softmax of zero priors = 1/64). Pure stream;
// unrolled x2 (16 LDG.128 in flight per warp) to maximize MLP.
// ---------------------------------------------------------------------------
__device__ __forceinline__ void phase_uniform(
    int b, int slice, int wb, int wloc, int lane, const float4* base,
    const float* __restrict__ bias, float* __restrict__ dout, float4* sbuf)
{
    float4 acc[8];
#pragma unroll
    for (int k = 0; k < 8; k++) acc[k] = make_float4(0.f, 0.f, 0.f, 0.f);

    for (int ii = 0; ii < IPW; ii += 2) {
        const float4* r0 = base + (size_t)ii * 256;
        const float4* r1 = base + (size_t)(ii + 1) * 256;
        float4 v0[8], v1[8];
#pragma unroll
        for (int k = 0; k < 8; k++) v0[k] = r0[lane + 32 * k];
#pragma unroll
        for (int k = 0; k < 8; k++) v1[k] = r1[lane + 32 * k];
#pragma unroll
        for (int k = 0; k < 8; k++) {
            acc[k].x += v0[k].x + v1[k].x;
            acc[k].y += v0[k].y + v1[k].y;
            acc[k].z += v0[k].z + v1[k].z;
            acc[k].w += v0[k].w + v1[k].w;
        }
    }
#pragma unroll
    for (int k = 0; k < 8; k++) {
        acc[k].x *= 0.015625f; acc[k].y *= 0.015625f;   // 1/64 exact
        acc[k].z *= 0.015625f; acc[k].w *= 0.015625f;
    }

    finish_tail<1, 0>(b, slice, acc, wloc, lane, bias, dout, sbuf);
}

// ---------------------------------------------------------------------------
// Weighted phase: p_j = dot(x[j,:], ow[j,:]); a = softmax_j(p); acc += a_j*x.
// REVERSE: back-to-front traversal (zigzag L2/L1 reuse across phases).
// Lane mapping: float4 f = lane + 32*k -> j = (lane>>2) + 8k, d = (lane&3)*4.
// ---------------------------------------------------------------------------
template<int OW_MODE, int FINAL_OUT, int REVERSE>
__device__ __forceinline__ void phase_weighted(
    int b, int slice, int wb, int wloc, int lane, const float4* base,
    const float* __restrict__ bias, float* __restrict__ dout, float4* sbuf)
{
    float4 w[8];
    const float4* owp = reinterpret_cast<const float4*>(g_ow) + (size_t)b * 256;
#pragma unroll
    for (int k = 0; k < 8; k++) w[k] = __ldcg(owp + lane + 32 * k);

    float4 acc[8];
#pragma unroll
    for (int k = 0; k < 8; k++) acc[k] = make_float4(0.f, 0.f, 0.f, 0.f);

    for (int it = 0; it < IPW; it++) {
        const int ii = REVERSE ? (IPW - 1 - it) : it;
        const float4* rowp = base + (size_t)ii * 256;
        float4 xv[8];
#pragma unroll
        for (int k = 0; k < 8; k++) xv[k] = rowp[lane + 32 * k];

        float p[8];
#pragma unroll
        for (int k = 0; k < 8; k++) {
            float t = xv[k].x * w[k].x + xv[k].y * w[k].y
                    + xv[k].z * w[k].z + xv[k].w * w[k].w;
            t += __shfl_xor_sync(0xffffffffu, t, 1);
            t += __shfl_xor_sync(0xffffffffu, t, 2);
            p[k] = t;   // dot over d=16, replicated within 4-lane group
        }
        // softmax over all 64 j
        float m = p[0];
#pragma unroll
        for (int k = 1; k < 8; k++) m = fmaxf(m, p[k]);
        m = fmaxf(m, __shfl_xor_sync(0xffffffffu, m, 4));
        m = fmaxf(m, __shfl_xor_sync(0xffffffffu, m, 8));
        m = fmaxf(m, __shfl_xor_sync(0xffffffffu, m, 16));
        float a[8], s = 0.f;
#pragma unroll
        for (int k = 0; k < 8; k++) { a[k] = __expf(p[k] - m); s += a[k]; }
        s += __shfl_xor_sync(0xffffffffu, s, 4);
        s += __shfl_xor_sync(0xffffffffu, s, 8);
        s += __shfl_xor_sync(0xffffffffu, s, 16);
        float inv = 1.0f / s;
#pragma unroll
        for (int k = 0; k < 8; k++) {
            float ak = a[k] * inv;
            acc[k].x = fmaf(ak, xv[k].x, acc[k].x);
            acc[k].y = fmaf(ak, xv[k].y, acc[k].y);
            acc[k].z = fmaf(ak, xv[k].z, acc[k].z);
            acc[k].w = fmaf(ak, xv[k].w, acc[k].w);
        }
    }

    finish_tail<OW_MODE, FINAL_OUT>(b, slice, acc, wloc, lane, bias, dout, sbuf);
}

// ---------------------------------------------------------------------------
// Single persistent kernel: phase0 (fwd) | barrier | phase1 (rev) | barrier |
// phase2 (fwd). One launch: no L1 flush between phases, no launch gaps.
// ---------------------------------------------------------------------------
__global__ void __launch_bounds__(256, 2)
router_fused(const float* __restrict__ x, const float* __restrict__ bias,
             float* __restrict__ dout)
{
    const int b     = blockIdx.x >> 3;
    const int slice = blockIdx.x & 7;
    const int wloc  = threadIdx.x >> 5;
    const int wb    = (slice << 3) | wloc;       // warp id within b: 0..63
    const int lane  = threadIdx.x & 31;

    __shared__ float4 sbuf[WPBLK * 256];         // 32 KB, reused across phases

    const float4* base = reinterpret_cast<const float4*>(x)
        + ((size_t)b * NIN + (size_t)wb * IPW) * 256;

    // Phase 0 (forward): uniform 1/64; g_ow = out0
    phase_uniform(b, slice, wb, wloc, lane, base, bias, dout, sbuf);
    grid_barrier();
    // Phase 1 (REVERSE): softmax(dot(x, out0)); g_ow = out0 + out1
    phase_weighted<2, 0, 1>(b, slice, wb, wloc, lane, base, bias, dout, sbuf);
    grid_barrier();
    // Phase 2 (forward): softmax(dot(x, out0+out1)); write output
    phase_weighted<0, 1, 0>(b, slice, wb, wloc, lane, base, bias, dout, sbuf);
}

extern "C" void kernel_launch(void* const* d_in, const int* in_sizes, int n_in,
                              void* d_out, int out_size)
{
    const float* x    = (const float*)d_in[0];   // [32, 2048, 64, 16]
    const float* bias = (const float*)d_in[1];   // [64, 16]
    float* out = (float*)d_out;                  // [32, 64, 16]

    (void)in_sizes; (void)n_in; (void)out_size;

    router_fused<<<GRID, 256>>>(x, bias, out);
}

// round 9
// speedup vs baseline: 1.5185x; 1.0009x over previous
#include <cuda_runtime.h>

// Problem constants
#define NB    32     // batch
#define GROUP 16     // batches per group (group working set = 128 MB ~ L2)
#define NIN   2048   // input capsules
#define ROW   1024   // NOUT*DD floats per (b,i) row
#define SLICES 16    // blocks per batch item (grid = GROUP*SLICES = 256 = 1 wave)
#define WPBLK  8     // warps per block
#define IPW   16     // input rows per warp (NIN / (SLICES*WPBLK))

// Scratch (static device memory; no runtime allocation)
__device__ float g_partials[NB * SLICES * ROW];  // 2 MB, L2-resident
__device__ float g_ow[NB * ROW];                 // out0 (round1) / out0+out1 (round2)
__device__ int   g_cnt[NB];                      // zero-init; self-resetting

// ---------------------------------------------------------------------------
// Fused tail: in-block reduce (8 warps -> 1 partial per block), then the LAST
// block of each batch reduces the SLICES partials in fixed order, adds bias,
// squashes, updates g_ow / writes output, resets the counter (replay-safe).
// ---------------------------------------------------------------------------
template<int OW_MODE, int FINAL_OUT>
__device__ __forceinline__ void finish_tail(
    int b, int slice, float4 acc[8], int wloc, int lane,
    const float* __restrict__ bias, float* __restrict__ dout)
{
    __shared__ float4 sbuf[WPBLK * 256];   // 32 KB
#pragma unroll
    for (int k = 0; k < 8; k++) sbuf[wloc * 256 + lane + 32 * k] = acc[k];
    __syncthreads();

    const int t = threadIdx.x;
    float4 s = make_float4(0.f, 0.f, 0.f, 0.f);
#pragma unroll
    for (int w2 = 0; w2 < WPBLK; w2++) {
        float4 v = sbuf[w2 * 256 + t];
        s.x += v.x; s.y += v.y; s.z += v.z; s.w += v.w;
    }
    reinterpret_cast<float4*>(g_partials)[((size_t)b * SLICES + slice) * 256 + t] = s;
    __threadfence();

    __shared__ int isLast;
    if (t == 0) {
        int old = atomicAdd(&g_cnt[b], 1);
        isLast = (old == SLICES - 1);
    }
    __syncthreads();
    if (!isLast) return;

    // Last block for this batch: all partials visible (fence + atomic order).
    const float4* pp = reinterpret_cast<const float4*>(g_partials) + (size_t)b * SLICES * 256;
    float4 r = make_float4(0.f, 0.f, 0.f, 0.f);
#pragma unroll
    for (int s2 = 0; s2 < SLICES; s2++) {
        float4 v = __ldcg(pp + s2 * 256 + t);   // L2 (other SMs wrote these)
        r.x += v.x; r.y += v.y; r.z += v.z; r.w += v.w;
    }
    float4 bb = reinterpret_cast<const float4*>(bias)[t];
    r.x += bb.x; r.y += bb.y; r.z += bb.z; r.w += bb.w;

    // squash over d=16 (4 threads per capsule j)
    float n2 = r.x * r.x + r.y * r.y + r.z * r.z + r.w * r.w;
    n2 += __shfl_xor_sync(0xffffffffu, n2, 1);
    n2 += __shfl_xor_sync(0xffffffffu, n2, 2);
    float scale = n2 / ((1.0f + n2) * sqrtf(n2 + 1e-7f));
    float4 o = make_float4(r.x * scale, r.y * scale, r.z * scale, r.w * scale);

    if (FINAL_OUT)
        reinterpret_cast<float4*>(dout)[b * 256 + t] = o;
    if (OW_MODE == 1) {
        reinterpret_cast<float4*>(g_ow)[b * 256 + t] = o;
    } else if (OW_MODE == 2) {
        float4 c = reinterpret_cast<const float4*>(g_ow)[b * 256 + t];
        c.x += o.x; c.y += o.y; c.z += o.z; c.w += o.w;
        reinterpret_cast<float4*>(g_ow)[b * 256 + t] = c;
    }

    if (t == 0) g_cnt[b] = 0;   // reset for next round / next graph replay
}

// ---------------------------------------------------------------------------
// Pass kernel over ONE GROUP of 16 batches. One warp processes IPW contiguous
// rows of x[b, i, :, :]. UNIFORM=1: a = 1/64 exactly (softmax of zero priors).
// REVERSE: back-to-front traversal -> zigzag L2 reuse across passes of the
// same group (group working set ~ L2 capacity).
// Lane mapping: float4 f = lane + 32*k -> j = (lane>>2) + 8k, d = (lane&3)*4.
// ---------------------------------------------------------------------------
template<int UNIFORM, int OW_MODE, int FINAL_OUT, int REVERSE>
__global__ void __launch_bounds__(256, 2)
route_pass(const float* __restrict__ x, const float* __restrict__ bias,
           float* __restrict__ dout, int b0)
{
    const int b     = b0 + (blockIdx.x >> 4);    // 16 slices per batch
    const int slice = blockIdx.x & 15;
    const int wloc  = threadIdx.x >> 5;
    const int wb    = (slice << 3) | wloc;       // warp id within b: 0..127
    const int lane  = threadIdx.x & 31;

    float4 w[8];
    if (!UNIFORM) {
        const float4* owp = reinterpret_cast<const float4*>(g_ow) + (size_t)b * 256;
#pragma unroll
        for (int k = 0; k < 8; k++) w[k] = owp[lane + 32 * k];
    }

    float4 acc[8];
#pragma unroll
    for (int k = 0; k < 8; k++) acc[k] = make_float4(0.f, 0.f, 0.f, 0.f);

    const float4* base = reinterpret_cast<const float4*>(x)
        + ((size_t)b * NIN + (size_t)wb * IPW) * 256;

    for (int it = 0; it < IPW; it++) {
        const int ii = REVERSE ? (IPW - 1 - it) : it;
        const float4* rowp = base + (size_t)ii * 256;
        float4 xv[8];
#pragma unroll
        for (int k = 0; k < 8; k++) xv[k] = rowp[lane + 32 * k];   // plain: L2 retain

        if (UNIFORM) {
#pragma unroll
            for (int k = 0; k < 8; k++) {
                acc[k].x += xv[k].x; acc[k].y += xv[k].y;
                acc[k].z += xv[k].z; acc[k].w += xv[k].w;
            }
        } else {
            float p[8];
#pragma unroll
            for (int k = 0; k < 8; k++) {
                float t = xv[k].x * w[k].x + xv[k].y * w[k].y
                        + xv[k].z * w[k].z + xv[k].w * w[k].w;
                t += __shfl_xor_sync(0xffffffffu, t, 1);
                t += __shfl_xor_sync(0xffffffffu, t, 2);
                p[k] = t;   // dot over d=16, replicated within 4-lane group
            }
            // softmax over all 64 j
            float m = p[0];
#pragma unroll
            for (int k = 1; k < 8; k++) m = fmaxf(m, p[k]);
            m = fmaxf(m, __shfl_xor_sync(0xffffffffu, m, 4));
            m = fmaxf(m, __shfl_xor_sync(0xffffffffu, m, 8));
            m = fmaxf(m, __shfl_xor_sync(0xffffffffu, m, 16));
            float a[8], s = 0.f;
#pragma unroll
            for (int k = 0; k < 8; k++) { a[k] = __expf(p[k] - m); s += a[k]; }
            s += __shfl_xor_sync(0xffffffffu, s, 4);
            s += __shfl_xor_sync(0xffffffffu, s, 8);
            s += __shfl_xor_sync(0xffffffffu, s, 16);
            float inv = 1.0f / s;
#pragma unroll
            for (int k = 0; k < 8; k++) {
                float ak = a[k] * inv;
                acc[k].x = fmaf(ak, xv[k].x, acc[k].x);
                acc[k].y = fmaf(ak, xv[k].y, acc[k].y);
                acc[k].z = fmaf(ak, xv[k].z, acc[k].z);
                acc[k].w = fmaf(ak, xv[k].w, acc[k].w);
            }
        }
    }

    if (UNIFORM) {
#pragma unroll
        for (int k = 0; k < 8; k++) {
            acc[k].x *= 0.015625f; acc[k].y *= 0.015625f;   // 1/64 exact
            acc[k].z *= 0.015625f; acc[k].w *= 0.015625f;
        }
    }

    finish_tail<OW_MODE, FINAL_OUT>(b, slice, acc, wloc, lane, bias, dout);
}

extern "C" void kernel_launch(void* const* d_in, const int* in_sizes, int n_in,
                              void* d_out, int out_size)
{
    const float* x    = (const float*)d_in[0];   // [32, 2048, 64, 16]
    const float* bias = (const float*)d_in[1];   // [64, 16]
    float* out = (float*)d_out;                  // [32, 64, 16]

    (void)in_sizes; (void)n_in; (void)out_size;

    dim3 g(GROUP * SLICES), blk(256);            // 256 blocks = one wave

    // Batches are independent: run all 3 rounds on group A (128 MB ~ L2),
    // then group B. Zigzag (fwd, rev, fwd) within each group keeps passes
    // 1 and 2 almost entirely L2-resident.
    for (int b0 = 0; b0 < NB; b0 += GROUP) {
        // Round 0 (forward): uniform 1/64; g_ow[b] = out0
        route_pass<1, 1, 0, 0><<<g, blk>>>(x, bias, out, b0);
        // Round 1 (REVERSE): softmax(dot(x, out0)); g_ow = out0 + out1
        route_pass<0, 2, 0, 1><<<g, blk>>>(x, bias, out, b0);
        // Round 2 (forward): softmax(dot(x, out0+out1)); write output
        route_pass<0, 0, 1, 0><<<g, blk>>>(x, bias, out, b0);
    }
}

// round 10
// speedup vs baseline: 1.5634x; 1.0296x over previous
#include <cuda_runtime.h>

// Problem constants
#define NB   32      // batch
#define NIN  2048    // input capsules
#define ROW  1024    // NOUT*DD floats per (b,i) row
#define SLICES 8     // blocks per batch item (grid 256 = single resident wave)
#define WPBLK  8     // warps per block
#define IPW  32      // input rows per warp (NIN / (SLICES*WPBLK))

// Scratch (static device memory; no runtime allocation)
__device__ float g_partials[NB * SLICES * ROW];  // 1 MB, L2-resident
__device__ float g_ow[NB * ROW];                 // out0 (round1) / out0+out1 (round2)
__device__ int   g_cnt[NB];                      // zero-init; self-resetting

// ---------------------------------------------------------------------------
// Fused tail: in-block reduce (8 warps -> 1 partial per block), then the LAST
// block of each batch reduces the SLICES partials in fixed order, adds bias,
// squashes, updates g_ow / writes output, resets the counter (replay-safe).
// ---------------------------------------------------------------------------
template<int OW_MODE, int FINAL_OUT>
__device__ __forceinline__ void finish_tail(
    int b, int slice, float4 acc[8], int wloc, int lane, float4* sbuf,
    const float* __restrict__ bias, float* __restrict__ dout)
{
#pragma unroll
    for (int k = 0; k < 8; k++) sbuf[wloc * 256 + lane + 32 * k] = acc[k];
    __syncthreads();

    const int t = threadIdx.x;
    float4 s = make_float4(0.f, 0.f, 0.f, 0.f);
#pragma unroll
    for (int w2 = 0; w2 < WPBLK; w2++) {
        float4 v = sbuf[w2 * 256 + t];
        s.x += v.x; s.y += v.y; s.z += v.z; s.w += v.w;
    }
    reinterpret_cast<float4*>(g_partials)[((size_t)b * SLICES + slice) * 256 + t] = s;
    __threadfence();

    __shared__ int isLast;
    if (t == 0) {
        int old = atomicAdd(&g_cnt[b], 1);
        isLast = (old == SLICES - 1);
    }
    __syncthreads();
    if (!isLast) return;

    // Last block for this batch: all partials visible (fence + atomic order).
    const float4* pp = reinterpret_cast<const float4*>(g_partials) + (size_t)b * SLICES * 256;
    float4 r = make_float4(0.f, 0.f, 0.f, 0.f);
#pragma unroll
    for (int s2 = 0; s2 < SLICES; s2++) {
        float4 v = __ldcg(pp + s2 * 256 + t);
        r.x += v.x; r.y += v.y; r.z += v.z; r.w += v.w;
    }
    float4 bb = reinterpret_cast<const float4*>(bias)[t];
    r.x += bb.x; r.y += bb.y; r.z += bb.z; r.w += bb.w;

    // squash over d=16 (4 threads per capsule j)
    float n2 = r.x * r.x + r.y * r.y + r.z * r.z + r.w * r.w;
    n2 += __shfl_xor_sync(0xffffffffu, n2, 1);
    n2 += __shfl_xor_sync(0xffffffffu, n2, 2);
    float scale = n2 / ((1.0f + n2) * sqrtf(n2 + 1e-7f));
    float4 o = make_float4(r.x * scale, r.y * scale, r.z * scale, r.w * scale);

    if (FINAL_OUT)
        reinterpret_cast<float4*>(dout)[b * 256 + t] = o;
    if (OW_MODE == 1) {
        reinterpret_cast<float4*>(g_ow)[b * 256 + t] = o;
    } else if (OW_MODE == 2) {
        float4 c = reinterpret_cast<const float4*>(g_ow)[b * 256 + t];
        c.x += o.x; c.y += o.y; c.z += o.z; c.w += o.w;
        reinterpret_cast<float4*>(g_ow)[b * 256 + t] = c;
    }

    if (t == 0) g_cnt[b] = 0;   // reset for next round / next graph replay
}

// ---------------------------------------------------------------------------
// Pass 0: uniform weights (softmax of zero priors = 1/64). Pure read stream,
// unrolled x2 rows = 16 LDG.128 in flight per warp.
// ---------------------------------------------------------------------------
__global__ void __launch_bounds__(256, 2)
route_pass0(const float* __restrict__ x, const float* __restrict__ bias,
            float* __restrict__ dout)
{
    const int b     = blockIdx.x >> 3;
    const int slice = blockIdx.x & 7;
    const int wloc  = threadIdx.x >> 5;
    const int wb    = (slice << 3) | wloc;
    const int lane  = threadIdx.x & 31;

    __shared__ float4 sbuf[WPBLK * 256];   // 32 KB (tail)

    float4 acc[8];
#pragma unroll
    for (int k = 0; k < 8; k++) acc[k] = make_float4(0.f, 0.f, 0.f, 0.f);

    const float4* base = reinterpret_cast<const float4*>(x)
        + ((size_t)b * NIN + (size_t)wb * IPW) * 256;

    for (int ii = 0; ii < IPW; ii += 2) {
        const float4* r0 = base + (size_t)ii * 256;
        const float4* r1 = base + (size_t)(ii + 1) * 256;
        float4 v0[8], v1[8];
#pragma unroll
        for (int k = 0; k < 8; k++) v0[k] = r0[lane + 32 * k];
#pragma unroll
        for (int k = 0; k < 8; k++) v1[k] = r1[lane + 32 * k];
#pragma unroll
        for (int k = 0; k < 8; k++) {
            acc[k].x += v0[k].x + v1[k].x;
            acc[k].y += v0[k].y + v1[k].y;
            acc[k].z += v0[k].z + v1[k].z;
            acc[k].w += v0[k].w + v1[k].w;
        }
    }
#pragma unroll
    for (int k = 0; k < 8; k++) {
        acc[k].x *= 0.015625f; acc[k].y *= 0.015625f;   // 1/64 exact
        acc[k].z *= 0.015625f; acc[k].w *= 0.015625f;
    }

    finish_tail<1, 0>(b, slice, acc, wloc, lane, sbuf, bias, dout);
}

// ---------------------------------------------------------------------------
// Weighted pass: p_j = dot(x[j,:], ow[j,:]); a = softmax_j(p); acc += a_j*x.
// w lives in SHARED (frees 32 regs); loop unrolled x2 rows -> up to 16 LDG.128
// in flight per warp. REVERSE: zigzag traversal for cross-pass L2 reuse.
// Lane mapping: float4 f = lane + 32*k -> j = (lane>>2) + 8k, d = (lane&3)*4.
// ---------------------------------------------------------------------------
template<int OW_MODE, int FINAL_OUT, int REVERSE>
__global__ void __launch_bounds__(256, 2)
route_passW(const float* __restrict__ x, const float* __restrict__ bias,
            float* __restrict__ dout)
{
    const int b     = blockIdx.x >> 3;
    const int slice = blockIdx.x & 7;
    const int wloc  = threadIdx.x >> 5;
    const int wb    = (slice << 3) | wloc;
    const int lane  = threadIdx.x & 31;

    __shared__ float4 wsh[256];            // routing weight vector for this b (4 KB)
    __shared__ float4 sbuf[WPBLK * 256];   // 32 KB (tail)

    {
        const float4* owp = reinterpret_cast<const float4*>(g_ow) + (size_t)b * 256;
        wsh[threadIdx.x] = owp[threadIdx.x];
    }
    __syncthreads();

    float4 acc[8];
#pragma unroll
    for (int k = 0; k < 8; k++) acc[k] = make_float4(0.f, 0.f, 0.f, 0.f);

    const float4* base = reinterpret_cast<const float4*>(x)
        + ((size_t)b * NIN + (size_t)wb * IPW) * 256;

    for (int it = 0; it < IPW; it += 2) {
        const int ii0 = REVERSE ? (IPW - 1 - it) : it;
        const int ii1 = REVERSE ? (IPW - 2 - it) : (it + 1);
        const float4* r0 = base + (size_t)ii0 * 256;
        const float4* r1 = base + (size_t)ii1 * 256;

        float4 xv0[8], xv1[8];
#pragma unroll
        for (int k = 0; k < 8; k++) xv0[k] = r0[lane + 32 * k];
#pragma unroll
        for (int k = 0; k < 8; k++) xv1[k] = r1[lane + 32 * k];

        float p0[8], p1[8];
#pragma unroll
        for (int k = 0; k < 8; k++) {
            float4 w = wsh[lane + 32 * k];
            float t0 = xv0[k].x * w.x + xv0[k].y * w.y + xv0[k].z * w.z + xv0[k].w * w.w;
            float t1 = xv1[k].x * w.x + xv1[k].y * w.y + xv1[k].z * w.z + xv1[k].w * w.w;
            t0 += __shfl_xor_sync(0xffffffffu, t0, 1);
            t1 += __shfl_xor_sync(0xffffffffu, t1, 1);
            t0 += __shfl_xor_sync(0xffffffffu, t0, 2);
            t1 += __shfl_xor_sync(0xffffffffu, t1, 2);
            p0[k] = t0;   // dot over d=16, replicated within 4-lane group
            p1[k] = t1;
        }
        // softmax over all 64 j (two independent rows interleaved)
        float m0 = p0[0], m1 = p1[0];
#pragma unroll
        for (int k = 1; k < 8; k++) { m0 = fmaxf(m0, p0[k]); m1 = fmaxf(m1, p1[k]); }
        m0 = fmaxf(m0, __shfl_xor_sync(0xffffffffu, m0, 4));
        m1 = fmaxf(m1, __shfl_xor_sync(0xffffffffu, m1, 4));
        m0 = fmaxf(m0, __shfl_xor_sync(0xffffffffu, m0, 8));
        m1 = fmaxf(m1, __shfl_xor_sync(0xffffffffu, m1, 8));
        m0 = fmaxf(m0, __shfl_xor_sync(0xffffffffu, m0, 16));
        m1 = fmaxf(m1, __shfl_xor_sync(0xffffffffu, m1, 16));
        float a0[8], a1[8], s0 = 0.f, s1 = 0.f;
#pragma unroll
        for (int k = 0; k < 8; k++) {
            a0[k] = __expf(p0[k] - m0); s0 += a0[k];
            a1[k] = __expf(p1[k] - m1); s1 += a1[k];
        }
        s0 += __shfl_xor_sync(0xffffffffu, s0, 4);
        s1 += __shfl_xor_sync(0xffffffffu, s1, 4);
        s0 += __shfl_xor_sync(0xffffffffu, s0, 8);
        s1 += __shfl_xor_sync(0xffffffffu, s1, 8);
        s0 += __shfl_xor_sync(0xffffffffu, s0, 16);
        s1 += __shfl_xor_sync(0xffffffffu, s1, 16);
        float inv0 = 1.0f / s0, inv1 = 1.0f / s1;
#pragma unroll
        for (int k = 0; k < 8; k++) {
            float ak0 = a0[k] * inv0;
            float ak1 = a1[k] * inv1;
            acc[k].x = fmaf(ak1, xv1[k].x, fmaf(ak0, xv0[k].x, acc[k].x));
            acc[k].y = fmaf(ak1, xv1[k].y, fmaf(ak0, xv0[k].y, acc[k].y));
            acc[k].z = fmaf(ak1, xv1[k].z, fmaf(ak0, xv0[k].z, acc[k].z));
            acc[k].w = fmaf(ak1, xv1[k].w, fmaf(ak0, xv0[k].w, acc[k].w));
        }
    }

    finish_tail<OW_MODE, FINAL_OUT>(b, slice, acc, wloc, lane, sbuf, bias, dout);
}

extern "C" void kernel_launch(void* const* d_in, const int* in_sizes, int n_in,
                              void* d_out, int out_size)
{
    const float* x    = (const float*)d_in[0];   // [32, 2048, 64, 16]
    const float* bias = (const float*)d_in[1];   // [64, 16]
    float* out = (float*)d_out;                  // [32, 64, 16]

    (void)in_sizes; (void)n_in; (void)out_size;

    dim3 g(NB * SLICES), blk(256);

    // Round 0 (forward): uniform 1/64; g_ow = out0
    route_pass0<<<g, blk>>>(x, bias, out);
    // Round 1 (REVERSE): softmax(dot(x, out0)); g_ow = out0 + out1
    route_passW<2, 0, 1><<<g, blk>>>(x, bias, out);
    // Round 2 (forward): softmax(dot(x, out0+out1)); write output
    route_passW<0, 1, 0><<<g, blk>>>(x, bias, out);
}